// round 2
// baseline (speedup 1.0000x reference)
#include <cuda_runtime.h>
#include <cstdint>
#include <cstddef>

#define MAXN 131072

// scratch for q/k/v projections (device globals: no allocation allowed)
__device__ float g_q[MAXN * 64];
__device__ float g_k[MAXN * 64];
__device__ float g_v[MAXN * 64];

// ---- packed fp32x2 ops (sm_103a FFMA2 path; 2x fp32 throughput) ----
__device__ __forceinline__ float2 fma2(float2 a, float2 b, float2 c) {
    float2 d;
    asm("fma.rn.f32x2 %0, %1, %2, %3;"
        : "=l"(*(unsigned long long*)&d)
        : "l"(*(unsigned long long*)&a),
          "l"(*(unsigned long long*)&b),
          "l"(*(unsigned long long*)&c));
    return d;
}
__device__ __forceinline__ float2 add2(float2 a, float2 b) {
    float2 d;
    asm("add.rn.f32x2 %0, %1, %2;"
        : "=l"(*(unsigned long long*)&d)
        : "l"(*(unsigned long long*)&a),
          "l"(*(unsigned long long*)&b));
    return d;
}

// ============================================================================
// Kernel 1: q/k/v = x @ W + b   (x:[N,64], W:[64,64])
// 64-row tile in smem, W in smem, thread computes 2 rows x 8 cols via FFMA2.
// grid = (ceil(N/64), 3); blockIdx.y selects matrix.
// ============================================================================
__global__ __launch_bounds__(256) void qkv_kernel(
    const float* __restrict__ x,
    const float* __restrict__ Wq, const float* __restrict__ bq,
    const float* __restrict__ Wk, const float* __restrict__ bk,
    const float* __restrict__ Wv, const float* __restrict__ bv,
    int N)
{
    __shared__ __align__(16) float xs[64 * 64];
    __shared__ __align__(16) float ws[64 * 64];
    const int tid = threadIdx.x;
    const int rowBase = blockIdx.x * 64;

    const float* W; const float* bia; float* out;
    if (blockIdx.y == 0)      { W = Wq; bia = bq; out = g_q; }
    else if (blockIdx.y == 1) { W = Wk; bia = bk; out = g_k; }
    else                      { W = Wv; bia = bv; out = g_v; }

    // load 64-row x tile (zero-pad past N) and full W
    for (int e = tid; e < 1024; e += 256) {
        int r = e >> 4, c4 = e & 15;
        float4 v = make_float4(0.f, 0.f, 0.f, 0.f);
        if (rowBase + r < N)
            v = *(const float4*)(x + (size_t)(rowBase + r) * 64 + c4 * 4);
        *(float4*)(xs + r * 64 + c4 * 4) = v;
    }
    for (int e = tid; e < 1024; e += 256)
        *(float4*)(ws + e * 4) = *(const float4*)(W + e * 4);
    __syncthreads();

    const int ty = tid >> 3, tx = tid & 7;
    const int c0 = tx * 8;
    const int r0 = ty, r1 = ty + 32;

    float2 acc0[4], acc1[4];
#pragma unroll
    for (int q = 0; q < 4; q++) {
        float2 b2 = *(const float2*)(bia + c0 + q * 2);
        acc0[q] = b2; acc1[q] = b2;
    }
#pragma unroll 4
    for (int k = 0; k < 64; k++) {
        float xa = xs[r0 * 64 + k];
        float xb = xs[r1 * 64 + k];
        float2 xa2 = make_float2(xa, xa);
        float2 xb2 = make_float2(xb, xb);
        const float2* wr = (const float2*)(ws + k * 64 + c0);
#pragma unroll
        for (int q = 0; q < 4; q++) {
            float2 wv = wr[q];
            acc0[q] = fma2(xa2, wv, acc0[q]);
            acc1[q] = fma2(xb2, wv, acc1[q]);
        }
    }
    if (rowBase + r0 < N) {
        *(float4*)(out + (size_t)(rowBase + r0) * 64 + c0) =
            make_float4(acc0[0].x, acc0[0].y, acc0[1].x, acc0[1].y);
        *(float4*)(out + (size_t)(rowBase + r0) * 64 + c0 + 4) =
            make_float4(acc0[2].x, acc0[2].y, acc0[3].x, acc0[3].y);
    }
    if (rowBase + r1 < N) {
        *(float4*)(out + (size_t)(rowBase + r1) * 64 + c0) =
            make_float4(acc1[0].x, acc1[0].y, acc1[1].x, acc1[1].y);
        *(float4*)(out + (size_t)(rowBase + r1) * 64 + c0 + 4) =
            make_float4(acc1[2].x, acc1[2].y, acc1[3].x, acc1[3].y);
    }
}

// ============================================================================
// Kernel 2: fused pe-MLP + relation MLP + softmax + aggregation.
// 16 lanes per point (2 points per warp, 16 points per 256-thread block).
// Phase A: lane = neighbor (gathered k row, MLP in registers, shfl softmax).
// Phase B: lane = 4 channels (coalesced v-row gather, weighted sum).
// ============================================================================
struct __align__(16) K2C {
    float s1[64], bb1[64];
    float r0[64], r1[64], r2[64], rb[64];      // raw Wp2 rows + bp2 (phase B)
    float ws0[64], ws1[64], ws2[64], wsb[64];  // s1-scaled rows + s1*bp2 (phase A)
    float wa[512];                             // Wa [64][8]
    float wbm[64];                             // Wb [8][8]
    float s2[8], bb2[8], ba[8], bw[8];
    float wp1[9], bp1v[3], spv[3], bpv[3];
};

__global__ __launch_bounds__(256) void attn_kernel(
    const float* __restrict__ p,  const int* __restrict__ idx,
    const float* __restrict__ Wp1, const float* __restrict__ bp1,
    const float* __restrict__ gp,  const float* __restrict__ bp,
    const float* __restrict__ Wp2, const float* __restrict__ bp2,
    const float* __restrict__ g1,  const float* __restrict__ bb1,
    const float* __restrict__ Wa,  const float* __restrict__ ba,
    const float* __restrict__ g2,  const float* __restrict__ bb2,
    const float* __restrict__ Wb,  const float* __restrict__ bw,
    float* __restrict__ outp, int N)
{
    __shared__ K2C cst;
    __shared__ __align__(16) float  xq_s[16][64];   // bb1 - q*s1 (transformed)
    __shared__ __align__(16) float4 h_s[16][16];    // post-relu pe hidden (3 + pad)
    __shared__ __align__(16) float  w_s[16][16][8]; // softmax weights
    __shared__ int idx_s[16][16];

    const int tid = threadIdx.x;
    const float RSQ = rsqrtf(1.f + 1e-5f);

    // ---- constant prep ----
    if (tid < 64) {
        float s1v = g1[tid] * RSQ;
        cst.s1[tid]  = s1v;
        cst.bb1[tid] = bb1[tid];
        float w0 = Wp2[tid], w1 = Wp2[64 + tid], w2 = Wp2[128 + tid], bb = bp2[tid];
        cst.r0[tid] = w0;        cst.r1[tid] = w1;
        cst.r2[tid] = w2;        cst.rb[tid] = bb;
        cst.ws0[tid] = w0 * s1v; cst.ws1[tid] = w1 * s1v;
        cst.ws2[tid] = w2 * s1v; cst.wsb[tid] = bb * s1v;
        cst.wbm[tid] = Wb[tid];
    }
    for (int e = tid; e < 512; e += 256) cst.wa[e] = Wa[e];
    if (tid < 8) {
        cst.s2[tid] = g2[tid] * RSQ;
        cst.bb2[tid] = bb2[tid];
        cst.ba[tid]  = ba[tid];
        cst.bw[tid]  = bw[tid];
    }
    if (tid < 9) cst.wp1[tid] = Wp1[tid];
    if (tid < 3) { cst.bp1v[tid] = bp1[tid]; cst.spv[tid] = gp[tid] * RSQ; cst.bpv[tid] = bp[tid]; }
    __syncthreads();

    const int pt  = tid >> 4;
    const int l16 = tid & 15;
    const int i0  = blockIdx.x * 16 + pt;
    const int i   = (i0 < N) ? i0 : 0;   // clamp; store is guarded

    // ---- per-neighbor prep: relative coords -> pe hidden h ----
    const int j  = l16;
    const int nj = idx[i * 16 + j];
    idx_s[pt][j] = nj;

    float pix = p[i * 3 + 0], piy = p[i * 3 + 1], piz = p[i * 3 + 2];
    float prx = p[nj * 3 + 0] - pix;
    float pry = p[nj * 3 + 1] - piy;
    float prz = p[nj * 3 + 2] - piz;
    float h0, h1, h2;
    {
        float u0 = cst.bp1v[0] + prx * cst.wp1[0] + pry * cst.wp1[3] + prz * cst.wp1[6];
        float u1 = cst.bp1v[1] + prx * cst.wp1[1] + pry * cst.wp1[4] + prz * cst.wp1[7];
        float u2 = cst.bp1v[2] + prx * cst.wp1[2] + pry * cst.wp1[5] + prz * cst.wp1[8];
        h0 = fmaxf(fmaf(u0, cst.spv[0], cst.bpv[0]), 0.f);
        h1 = fmaxf(fmaf(u1, cst.spv[1], cst.bpv[1]), 0.f);
        h2 = fmaxf(fmaf(u2, cst.spv[2], cst.bpv[2]), 0.f);
    }
    h_s[pt][j] = make_float4(h0, h1, h2, 0.f);

    {   // transformed query per channel group: bb1 - q*s1
        float4 q4 = *(const float4*)(g_q + (size_t)i * 64 + l16 * 4);
        float4 s4 = *(const float4*)(cst.s1 + l16 * 4);
        float4 b4 = *(const float4*)(cst.bb1 + l16 * 4);
        float4 t;
        t.x = fmaf(-q4.x, s4.x, b4.x);
        t.y = fmaf(-q4.y, s4.y, b4.y);
        t.z = fmaf(-q4.z, s4.z, b4.z);
        t.w = fmaf(-q4.w, s4.w, b4.w);
        *(float4*)&xq_s[pt][l16 * 4] = t;
    }
    __syncwarp();

    // ---- phase A: relation MLP (64 -> 8), per-lane neighbor ----
    float2 h00 = make_float2(h0, h0), h11 = make_float2(h1, h1), h22 = make_float2(h2, h2);
    float2 a2[4];
#pragma unroll
    for (int q = 0; q < 4; q++) a2[q] = *(const float2*)(cst.ba + q * 2);

    const float4* kp = (const float4*)(g_k + (size_t)nj * 64);
#pragma unroll 4
    for (int c4 = 0; c4 < 16; c4++) {
        float4 kv  = kp[c4];
        float4 qb  = *(const float4*)&xq_s[pt][c4 * 4];
        float4 s4  = *(const float4*)(cst.s1  + c4 * 4);
        float4 w0  = *(const float4*)(cst.ws0 + c4 * 4);
        float4 w1  = *(const float4*)(cst.ws1 + c4 * 4);
        float4 w2  = *(const float4*)(cst.ws2 + c4 * 4);
        float4 wb4 = *(const float4*)(cst.wsb + c4 * 4);

        float2 pe01 = fma2(h00, make_float2(w0.x, w0.y),
                      fma2(h11, make_float2(w1.x, w1.y),
                      fma2(h22, make_float2(w2.x, w2.y), make_float2(wb4.x, wb4.y))));
        float2 pe23 = fma2(h00, make_float2(w0.z, w0.w),
                      fma2(h11, make_float2(w1.z, w1.w),
                      fma2(h22, make_float2(w2.z, w2.w), make_float2(wb4.z, wb4.w))));
        // relu arg = k*s1 + (bb1 - q*s1) + pe*s1
        float2 arg01 = fma2(make_float2(kv.x, kv.y), make_float2(s4.x, s4.y),
                            add2(make_float2(qb.x, qb.y), pe01));
        float2 arg23 = fma2(make_float2(kv.z, kv.w), make_float2(s4.z, s4.w),
                            add2(make_float2(qb.z, qb.w), pe23));
        float rv[4];
        rv[0] = fmaxf(arg01.x, 0.f); rv[1] = fmaxf(arg01.y, 0.f);
        rv[2] = fmaxf(arg23.x, 0.f); rv[3] = fmaxf(arg23.y, 0.f);
#pragma unroll
        for (int k = 0; k < 4; k++) {
            const float2* wac = (const float2*)(cst.wa + (c4 * 4 + k) * 8);
            float2 rr = make_float2(rv[k], rv[k]);
            a2[0] = fma2(rr, wac[0], a2[0]);
            a2[1] = fma2(rr, wac[1], a2[1]);
            a2[2] = fma2(rr, wac[2], a2[2]);
            a2[3] = fma2(rr, wac[3], a2[3]);
        }
    }

    // ---- second MLP (8 -> 8) ----
    float2 b2[4];
#pragma unroll
    for (int q = 0; q < 4; q++) b2[q] = *(const float2*)(cst.bw + q * 2);
#pragma unroll
    for (int m = 0; m < 8; m++) {
        float avm = (m & 1) ? a2[m >> 1].y : a2[m >> 1].x;
        float t = fmaxf(fmaf(avm, cst.s2[m], cst.bb2[m]), 0.f);
        float2 tt = make_float2(t, t);
        const float2* wr = (const float2*)(cst.wbm + m * 8);
        b2[0] = fma2(tt, wr[0], b2[0]);
        b2[1] = fma2(tt, wr[1], b2[1]);
        b2[2] = fma2(tt, wr[2], b2[2]);
        b2[3] = fma2(tt, wr[3], b2[3]);
    }

    // ---- softmax over 16 neighbors (xor-shfl within 16-lane group) ----
    float w8[8];
#pragma unroll
    for (int m = 0; m < 8; m++) {
        float v = (m & 1) ? b2[m >> 1].y : b2[m >> 1].x;
        float mx = v;
#pragma unroll
        for (int off = 8; off >= 1; off >>= 1)
            mx = fmaxf(mx, __shfl_xor_sync(0xffffffffu, mx, off));
        float e = __expf(v - mx);
        float s = e;
#pragma unroll
        for (int off = 8; off >= 1; off >>= 1)
            s += __shfl_xor_sync(0xffffffffu, s, off);
        w8[m] = __fdividef(e, s);
    }
    *(float4*)&w_s[pt][j][0] = make_float4(w8[0], w8[1], w8[2], w8[3]);
    *(float4*)&w_s[pt][j][4] = make_float4(w8[4], w8[5], w8[6], w8[7]);
    __syncwarp();

    // ---- phase B: channel-parallel aggregation (coalesced v gather) ----
    const int c0 = l16 * 4;
    const int m0 = (l16 & 1) * 4;
    float4 rr0 = *(const float4*)(cst.r0 + c0);
    float4 rr1 = *(const float4*)(cst.r1 + c0);
    float4 rr2 = *(const float4*)(cst.r2 + c0);
    float4 rrb = *(const float4*)(cst.rb + c0);
    float2 acc01 = make_float2(0.f, 0.f), acc23 = make_float2(0.f, 0.f);
#pragma unroll
    for (int jj = 0; jj < 16; jj++) {
        int nb    = idx_s[pt][jj];
        float4 h4 = h_s[pt][jj];
        float4 wv = *(const float4*)&w_s[pt][jj][m0];
        float4 v4 = *(const float4*)(g_v + (size_t)nb * 64 + c0);
        float2 hx = make_float2(h4.x, h4.x);
        float2 hy = make_float2(h4.y, h4.y);
        float2 hz = make_float2(h4.z, h4.z);
        float2 pe01 = fma2(hx, make_float2(rr0.x, rr0.y),
                      fma2(hy, make_float2(rr1.x, rr1.y),
                      fma2(hz, make_float2(rr2.x, rr2.y), make_float2(rrb.x, rrb.y))));
        float2 pe23 = fma2(hx, make_float2(rr0.z, rr0.w),
                      fma2(hy, make_float2(rr1.z, rr1.w),
                      fma2(hz, make_float2(rr2.z, rr2.w), make_float2(rrb.z, rrb.w))));
        acc01 = fma2(add2(make_float2(v4.x, v4.y), pe01), make_float2(wv.x, wv.y), acc01);
        acc23 = fma2(add2(make_float2(v4.z, v4.w), pe23), make_float2(wv.z, wv.w), acc23);
    }
    if (i0 < N)
        *(float4*)(outp + (size_t)i0 * 64 + c0) =
            make_float4(acc01.x, acc01.y, acc23.x, acc23.y);
}

// ============================================================================
extern "C" void kernel_launch(void* const* d_in, const int* in_sizes, int n_in,
                              void* d_out, int out_size) {
    const float* p   = (const float*)d_in[0];
    const float* x   = (const float*)d_in[1];
    const int*   idx = (const int*)d_in[2];
    const float* Wq  = (const float*)d_in[3];  const float* bq  = (const float*)d_in[4];
    const float* Wk  = (const float*)d_in[5];  const float* bk  = (const float*)d_in[6];
    const float* Wv  = (const float*)d_in[7];  const float* bv  = (const float*)d_in[8];
    const float* Wp1 = (const float*)d_in[9];  const float* bp1 = (const float*)d_in[10];
    const float* gp  = (const float*)d_in[11]; const float* bp  = (const float*)d_in[12];
    const float* Wp2 = (const float*)d_in[13]; const float* bp2 = (const float*)d_in[14];
    const float* g1  = (const float*)d_in[15]; const float* bb1 = (const float*)d_in[16];
    const float* Wa  = (const float*)d_in[17]; const float* ba  = (const float*)d_in[18];
    const float* g2  = (const float*)d_in[19]; const float* bb2 = (const float*)d_in[20];
    const float* Wb  = (const float*)d_in[21]; const float* bw  = (const float*)d_in[22];

    int N = in_sizes[0] / 3;
    if (N > MAXN) N = MAXN;  // scratch bound (problem shape is N=100000)

    dim3 grid1((N + 63) / 64, 3);
    qkv_kernel<<<grid1, 256>>>(x, Wq, bq, Wk, bk, Wv, bv, N);

    attn_kernel<<<(N + 15) / 16, 256>>>(p, idx, Wp1, bp1, gp, bp, Wp2, bp2,
                                        g1, bb1, Wa, ba, g2, bb2, Wb, bw,
                                        (float*)d_out, N);
}

// round 3
// speedup vs baseline: 1.0601x; 1.0601x over previous
#include <cuda_runtime.h>
#include <cstdint>
#include <cstddef>

#define MAXN 131072

// scratch for q/k/v projections (device globals: no allocation allowed)
__device__ float g_q[MAXN * 64];
__device__ float g_k[MAXN * 64];
__device__ float g_v[MAXN * 64];

// ---- packed fp32x2 ops (sm_103a FFMA2 path; 2x fp32 throughput) ----
__device__ __forceinline__ float2 fma2(float2 a, float2 b, float2 c) {
    float2 d;
    asm("fma.rn.f32x2 %0, %1, %2, %3;"
        : "=l"(*(unsigned long long*)&d)
        : "l"(*(unsigned long long*)&a),
          "l"(*(unsigned long long*)&b),
          "l"(*(unsigned long long*)&c));
    return d;
}
__device__ __forceinline__ float2 add2(float2 a, float2 b) {
    float2 d;
    asm("add.rn.f32x2 %0, %1, %2;"
        : "=l"(*(unsigned long long*)&d)
        : "l"(*(unsigned long long*)&a),
          "l"(*(unsigned long long*)&b));
    return d;
}

// ============================================================================
// Kernel 1: fused q/k/v = x @ [Wq|Wk|Wv] + b.  One x-tile load serves 3 GEMMs.
// 64-row tile; thread computes 2 rows x 24 cols (8 per matrix) via FFMA2.
// xs stride 65 -> conflict-free scalar LDS of x columns.
// ============================================================================
__global__ __launch_bounds__(256) void qkv_kernel(
    const float* __restrict__ x,
    const float* __restrict__ Wq, const float* __restrict__ bq,
    const float* __restrict__ Wk, const float* __restrict__ bk,
    const float* __restrict__ Wv, const float* __restrict__ bv,
    int N)
{
    __shared__ float xs[64 * 65];          // 16.6 KB (static)
    extern __shared__ float ws[];          // 64*192 floats = 48 KB (dynamic)
    const int tid = threadIdx.x;
    const int rowBase = blockIdx.x * 64;

    // fused weight: ws[k*192 + m*64 + c]
    {
        const float* Wm[3] = {Wq, Wk, Wv};
#pragma unroll
        for (int m = 0; m < 3; m++) {
            const float4* src = (const float4*)Wm[m];
            for (int e = tid; e < 1024; e += 256) {
                int k = e >> 4, c4 = e & 15;
                *(float4*)(ws + k * 192 + m * 64 + c4 * 4) = src[e];
            }
        }
    }
    // x tile (zero-pad past N), stride-65 rows
    for (int e = tid; e < 1024; e += 256) {
        int r = e >> 4, c4 = e & 15;
        float4 v = make_float4(0.f, 0.f, 0.f, 0.f);
        if (rowBase + r < N)
            v = *(const float4*)(x + (size_t)(rowBase + r) * 64 + c4 * 4);
        float* d = xs + r * 65 + c4 * 4;
        d[0] = v.x; d[1] = v.y; d[2] = v.z; d[3] = v.w;
    }
    __syncthreads();

    const int ty = tid >> 3, tx = tid & 7;   // ty: 0..31 row groups, tx: 0..7 col groups
    const int r0 = ty * 2, c0 = tx * 8;

    float2 acc[3][2][4];
#pragma unroll
    for (int q = 0; q < 4; q++) {
        float2 b0 = *(const float2*)(bq + c0 + q * 2);
        float2 b1 = *(const float2*)(bk + c0 + q * 2);
        float2 b2v = *(const float2*)(bv + c0 + q * 2);
#pragma unroll
        for (int r = 0; r < 2; r++) {
            acc[0][r][q] = b0; acc[1][r][q] = b1; acc[2][r][q] = b2v;
        }
    }

#pragma unroll 4
    for (int k = 0; k < 64; k++) {
        float xv0 = xs[(r0 + 0) * 65 + k];
        float xv1 = xs[(r0 + 1) * 65 + k];
        float2 xa = make_float2(xv0, xv0);
        float2 xb = make_float2(xv1, xv1);
        const float2* wr = (const float2*)(ws + k * 192);
#pragma unroll
        for (int m = 0; m < 3; m++) {
            const float2* wm = wr + m * 32 + tx * 4;
            float2 w0 = wm[0], w1 = wm[1], w2 = wm[2], w3 = wm[3];
            acc[m][0][0] = fma2(xa, w0, acc[m][0][0]);
            acc[m][0][1] = fma2(xa, w1, acc[m][0][1]);
            acc[m][0][2] = fma2(xa, w2, acc[m][0][2]);
            acc[m][0][3] = fma2(xa, w3, acc[m][0][3]);
            acc[m][1][0] = fma2(xb, w0, acc[m][1][0]);
            acc[m][1][1] = fma2(xb, w1, acc[m][1][1]);
            acc[m][1][2] = fma2(xb, w2, acc[m][1][2]);
            acc[m][1][3] = fma2(xb, w3, acc[m][1][3]);
        }
    }

    float* outs[3] = {g_q, g_k, g_v};
#pragma unroll
    for (int m = 0; m < 3; m++) {
#pragma unroll
        for (int r = 0; r < 2; r++) {
            int row = rowBase + r0 + r;
            if (row < N) {
                float* o = outs[m] + (size_t)row * 64 + c0;
                *(float4*)(o) = make_float4(acc[m][r][0].x, acc[m][r][0].y,
                                            acc[m][r][1].x, acc[m][r][1].y);
                *(float4*)(o + 4) = make_float4(acc[m][r][2].x, acc[m][r][2].y,
                                                acc[m][r][3].x, acc[m][r][3].y);
            }
        }
    }
}

// ============================================================================
// Kernel 2: fused attention.
// 16 lanes/point, 16 points/block. Channel chunks of 32:
//   stage (lane=channel): coalesced k gather + full BN/pe/ReLU arg -> rv
//     stored TRANSPOSED (c-major, stride 17; point stride 560 == 16 mod 32
//     -> conflict-free scalar LDS for both warp halves).
//   phase A (lane=neighbor): a[8] += rv[c] * Wa[c][:], pure smem scalar+wa.
// Then 8->8 MLP, shfl softmax, channel-parallel coalesced v aggregation.
// ============================================================================
struct __align__(16) K2C {
    float s1[64], bb1[64];
    float ws0[64], ws1[64], ws2[64], wsb[64];  // s1-scaled Wp2 rows + s1*bp2
    float r0[64], r1[64], r2[64], rb[64];      // raw Wp2 rows + bp2 (phase B)
    float wa[512];                             // Wa [64][8]
    float wbm[64];                             // Wb [8][8]
    float s2[8], bb2[8], ba[8], bw[8];
    float wp1[9], bp1v[3], spv[3], bpv[3];
};

#define RV_PT_STRIDE 560   // 32*17 + 16 pad; % 32 == 16 (bank-complementary halves)

__global__ __launch_bounds__(256) void attn_kernel(
    const float* __restrict__ p,  const int* __restrict__ idx,
    const float* __restrict__ Wp1, const float* __restrict__ bp1,
    const float* __restrict__ gp,  const float* __restrict__ bp,
    const float* __restrict__ Wp2, const float* __restrict__ bp2,
    const float* __restrict__ g1,  const float* __restrict__ bb1,
    const float* __restrict__ Wa,  const float* __restrict__ ba,
    const float* __restrict__ g2,  const float* __restrict__ bb2,
    const float* __restrict__ Wb,  const float* __restrict__ bw,
    float* __restrict__ outp, int N)
{
    __shared__ K2C cst;
    __shared__ __align__(16) float4 h_s[16][16];    // post-relu pe hidden
    __shared__ __align__(16) float  w_s[16][16][8]; // softmax weights
    __shared__ int idx_s[16][16];
    extern __shared__ float rv_s[];                 // 16 * RV_PT_STRIDE floats

    const int tid = threadIdx.x;
    const float RSQ = rsqrtf(1.f + 1e-5f);

    // ---- constant prep ----
    if (tid < 64) {
        float s1v = g1[tid] * RSQ;
        cst.s1[tid]  = s1v;
        cst.bb1[tid] = bb1[tid];
        float w0 = Wp2[tid], w1 = Wp2[64 + tid], w2 = Wp2[128 + tid], bb = bp2[tid];
        cst.r0[tid] = w0;        cst.r1[tid] = w1;
        cst.r2[tid] = w2;        cst.rb[tid] = bb;
        cst.ws0[tid] = w0 * s1v; cst.ws1[tid] = w1 * s1v;
        cst.ws2[tid] = w2 * s1v; cst.wsb[tid] = bb * s1v;
        cst.wbm[tid] = Wb[tid];
    }
    for (int e = tid; e < 512; e += 256) cst.wa[e] = Wa[e];
    if (tid < 8) {
        cst.s2[tid] = g2[tid] * RSQ;
        cst.bb2[tid] = bb2[tid];
        cst.ba[tid]  = ba[tid];
        cst.bw[tid]  = bw[tid];
    }
    if (tid < 9) cst.wp1[tid] = Wp1[tid];
    if (tid < 3) { cst.bp1v[tid] = bp1[tid]; cst.spv[tid] = gp[tid] * RSQ; cst.bpv[tid] = bp[tid]; }
    __syncthreads();

    const int pt = tid >> 4;
    const int l  = tid & 15;
    const int i0 = blockIdx.x * 16 + pt;
    const int i  = (i0 < N) ? i0 : 0;   // clamp; final store guarded

    // ---- prep: neighbor idx + pe hidden ----
    const int nj = idx[i * 16 + l];
    idx_s[pt][l] = nj;

    {
        float pix = p[i * 3 + 0], piy = p[i * 3 + 1], piz = p[i * 3 + 2];
        float prx = p[nj * 3 + 0] - pix;
        float pry = p[nj * 3 + 1] - piy;
        float prz = p[nj * 3 + 2] - piz;
        float u0 = cst.bp1v[0] + prx * cst.wp1[0] + pry * cst.wp1[3] + prz * cst.wp1[6];
        float u1 = cst.bp1v[1] + prx * cst.wp1[1] + pry * cst.wp1[4] + prz * cst.wp1[7];
        float u2 = cst.bp1v[2] + prx * cst.wp1[2] + pry * cst.wp1[5] + prz * cst.wp1[8];
        float h0 = fmaxf(fmaf(u0, cst.spv[0], cst.bpv[0]), 0.f);
        float h1 = fmaxf(fmaf(u1, cst.spv[1], cst.bpv[1]), 0.f);
        float h2 = fmaxf(fmaf(u2, cst.spv[2], cst.bpv[2]), 0.f);
        h_s[pt][l] = make_float4(h0, h1, h2, 0.f);
    }
    __syncwarp();

    float* rvp = rv_s + pt * RV_PT_STRIDE;

    float2 a2[4];
#pragma unroll
    for (int q = 0; q < 4; q++) a2[q] = *(const float2*)(cst.ba + q * 2);

#pragma unroll
    for (int cb = 0; cb < 64; cb += 32) {
        // per-lane channel constants for channels cA=cb+l, cB=cb+l+16 (registers)
        const int cA = cb + l, cB = cA + 16;
        float2 s1v = make_float2(cst.s1[cA], cst.s1[cB]);
        float2 xqv;
        {
            float qa = g_q[(size_t)i * 64 + cA];
            float qb = g_q[(size_t)i * 64 + cB];
            xqv = make_float2(fmaf(-qa, s1v.x, cst.bb1[cA]),
                              fmaf(-qb, s1v.y, cst.bb1[cB]));
        }
        float2 w0v = make_float2(cst.ws0[cA], cst.ws0[cB]);
        float2 w1v = make_float2(cst.ws1[cA], cst.ws1[cB]);
        float2 w2v = make_float2(cst.ws2[cA], cst.ws2[cB]);
        float2 wbv = make_float2(cst.wsb[cA], cst.wsb[cB]);

        // ---- stage: coalesced k gather -> rv (transposed, conflict-free) ----
#pragma unroll 4
        for (int jj = 0; jj < 16; jj++) {
            int nb = idx_s[pt][jj];
            const float* kr = g_k + (size_t)nb * 64 + cb;
            float2 kv = make_float2(kr[l], kr[l + 16]);
            float4 h4 = h_s[pt][jj];
            float2 pe = fma2(make_float2(h4.x, h4.x), w0v,
                        fma2(make_float2(h4.y, h4.y), w1v,
                        fma2(make_float2(h4.z, h4.z), w2v, wbv)));
            float2 arg = fma2(kv, s1v, add2(xqv, pe));
            rvp[l * 17 + jj]        = fmaxf(arg.x, 0.f);
            rvp[(l + 16) * 17 + jj] = fmaxf(arg.y, 0.f);
        }
        __syncwarp();

        // ---- phase A partial: a[8] += rv[c] * Wa[cb+c][:] ----
#pragma unroll
        for (int c = 0; c < 32; c++) {
            float rvv = rvp[c * 17 + l];               // lane = neighbor j
            const float2* war = (const float2*)(cst.wa + (cb + c) * 8);
            float2 rr = make_float2(rvv, rvv);
            a2[0] = fma2(rr, war[0], a2[0]);
            a2[1] = fma2(rr, war[1], a2[1]);
            a2[2] = fma2(rr, war[2], a2[2]);
            a2[3] = fma2(rr, war[3], a2[3]);
        }
        __syncwarp();
    }

    // ---- second MLP (8 -> 8) ----
    float2 b2[4];
#pragma unroll
    for (int q = 0; q < 4; q++) b2[q] = *(const float2*)(cst.bw + q * 2);
#pragma unroll
    for (int m = 0; m < 8; m++) {
        float avm = (m & 1) ? a2[m >> 1].y : a2[m >> 1].x;
        float t = fmaxf(fmaf(avm, cst.s2[m], cst.bb2[m]), 0.f);
        float2 tt = make_float2(t, t);
        const float2* wr = (const float2*)(cst.wbm + m * 8);
        b2[0] = fma2(tt, wr[0], b2[0]);
        b2[1] = fma2(tt, wr[1], b2[1]);
        b2[2] = fma2(tt, wr[2], b2[2]);
        b2[3] = fma2(tt, wr[3], b2[3]);
    }

    // ---- softmax over 16 neighbors (xor-shfl within 16-lane group) ----
    float w8[8];
#pragma unroll
    for (int m = 0; m < 8; m++) {
        float v = (m & 1) ? b2[m >> 1].y : b2[m >> 1].x;
        float mx = v;
#pragma unroll
        for (int off = 8; off >= 1; off >>= 1)
            mx = fmaxf(mx, __shfl_xor_sync(0xffffffffu, mx, off));
        float e = __expf(v - mx);
        float s = e;
#pragma unroll
        for (int off = 8; off >= 1; off >>= 1)
            s += __shfl_xor_sync(0xffffffffu, s, off);
        w8[m] = __fdividef(e, s);
    }
    *(float4*)&w_s[pt][l][0] = make_float4(w8[0], w8[1], w8[2], w8[3]);
    *(float4*)&w_s[pt][l][4] = make_float4(w8[4], w8[5], w8[6], w8[7]);
    __syncwarp();

    // ---- phase B: channel-parallel aggregation (coalesced v gather) ----
    const int c0 = l * 4;
    const int m0 = (l & 1) * 4;
    float4 rr0 = *(const float4*)(cst.r0 + c0);
    float4 rr1 = *(const float4*)(cst.r1 + c0);
    float4 rr2 = *(const float4*)(cst.r2 + c0);
    float4 rrb = *(const float4*)(cst.rb + c0);
    float2 acc01 = make_float2(0.f, 0.f), acc23 = make_float2(0.f, 0.f);
#pragma unroll
    for (int jj = 0; jj < 16; jj++) {
        int nb    = idx_s[pt][jj];
        float4 h4 = h_s[pt][jj];
        float4 wv = *(const float4*)&w_s[pt][jj][m0];
        float4 v4 = *(const float4*)(g_v + (size_t)nb * 64 + c0);
        float2 hx = make_float2(h4.x, h4.x);
        float2 hy = make_float2(h4.y, h4.y);
        float2 hz = make_float2(h4.z, h4.z);
        float2 pe01 = fma2(hx, make_float2(rr0.x, rr0.y),
                      fma2(hy, make_float2(rr1.x, rr1.y),
                      fma2(hz, make_float2(rr2.x, rr2.y), make_float2(rrb.x, rrb.y))));
        float2 pe23 = fma2(hx, make_float2(rr0.z, rr0.w),
                      fma2(hy, make_float2(rr1.z, rr1.w),
                      fma2(hz, make_float2(rr2.z, rr2.w), make_float2(rrb.z, rrb.w))));
        acc01 = fma2(add2(make_float2(v4.x, v4.y), pe01), make_float2(wv.x, wv.y), acc01);
        acc23 = fma2(add2(make_float2(v4.z, v4.w), pe23), make_float2(wv.z, wv.w), acc23);
    }
    if (i0 < N)
        *(float4*)(outp + (size_t)i0 * 64 + c0) =
            make_float4(acc01.x, acc01.y, acc23.x, acc23.y);
}

// ============================================================================
extern "C" void kernel_launch(void* const* d_in, const int* in_sizes, int n_in,
                              void* d_out, int out_size) {
    const float* p   = (const float*)d_in[0];
    const float* x   = (const float*)d_in[1];
    const int*   idx = (const int*)d_in[2];
    const float* Wq  = (const float*)d_in[3];  const float* bq  = (const float*)d_in[4];
    const float* Wk  = (const float*)d_in[5];  const float* bk  = (const float*)d_in[6];
    const float* Wv  = (const float*)d_in[7];  const float* bv  = (const float*)d_in[8];
    const float* Wp1 = (const float*)d_in[9];  const float* bp1 = (const float*)d_in[10];
    const float* gp  = (const float*)d_in[11]; const float* bp  = (const float*)d_in[12];
    const float* Wp2 = (const float*)d_in[13]; const float* bp2 = (const float*)d_in[14];
    const float* g1  = (const float*)d_in[15]; const float* bb1 = (const float*)d_in[16];
    const float* Wa  = (const float*)d_in[17]; const float* ba  = (const float*)d_in[18];
    const float* g2  = (const float*)d_in[19]; const float* bb2 = (const float*)d_in[20];
    const float* Wb  = (const float*)d_in[21]; const float* bw  = (const float*)d_in[22];

    int N = in_sizes[0] / 3;
    if (N > MAXN) N = MAXN;  // scratch bound (problem shape is N=100000)

    const int qkv_dyn  = 64 * 192 * (int)sizeof(float);       // 49152
    const int attn_dyn = 16 * RV_PT_STRIDE * (int)sizeof(float); // 35840
    cudaFuncSetAttribute(qkv_kernel,  cudaFuncAttributeMaxDynamicSharedMemorySize, qkv_dyn);
    cudaFuncSetAttribute(attn_kernel, cudaFuncAttributeMaxDynamicSharedMemorySize, attn_dyn);

    qkv_kernel<<<(N + 63) / 64, 256, qkv_dyn>>>(x, Wq, bq, Wk, bk, Wv, bv, N);

    attn_kernel<<<(N + 15) / 16, 256, attn_dyn>>>(p, idx, Wp1, bp1, gp, bp, Wp2, bp2,
                                                  g1, bb1, Wa, ba, g2, bb2, Wb, bw,
                                                  (float*)d_out, N);
}

// round 4
// speedup vs baseline: 1.3360x; 1.2602x over previous
#include <cuda_runtime.h>
#include <cstdint>
#include <cstddef>

#define MAXN 131072

// scratch (device globals: no allocation allowed)
__device__ float g_q[MAXN * 64];
__device__ float g_k[MAXN * 64];
__device__ float g_v[MAXN * 64];
__device__ float4 g_p4[MAXN];

// ---- packed fp32x2 ops (sm_103a FFMA2 path) ----
__device__ __forceinline__ float2 fma2(float2 a, float2 b, float2 c) {
    float2 d;
    asm("fma.rn.f32x2 %0, %1, %2, %3;"
        : "=l"(*(unsigned long long*)&d)
        : "l"(*(unsigned long long*)&a),
          "l"(*(unsigned long long*)&b),
          "l"(*(unsigned long long*)&c));
    return d;
}
__device__ __forceinline__ float2 add2(float2 a, float2 b) {
    float2 d;
    asm("add.rn.f32x2 %0, %1, %2;"
        : "=l"(*(unsigned long long*)&d)
        : "l"(*(unsigned long long*)&a),
          "l"(*(unsigned long long*)&b));
    return d;
}

// ============================================================================
// Kernel 1: fused q/k/v = x @ [Wq|Wk|Wv] + b, plus p -> g_p4 repack.
// 64-row tile; thread = 4 rows x (3 matrices x 4 cols).
// Weight reads: LDS.128 at word offset tx*4, tx=0..15 -> conflict-free
// (2-phase floor). x reads: 2-address broadcast scalars.
// ============================================================================
__global__ __launch_bounds__(256) void qkv_kernel(
    const float* __restrict__ x, const float* __restrict__ p,
    const float* __restrict__ Wq, const float* __restrict__ bq,
    const float* __restrict__ Wk, const float* __restrict__ bk,
    const float* __restrict__ Wv, const float* __restrict__ bv,
    int N)
{
    __shared__ float xs[64 * 65];          // 16.6 KB
    extern __shared__ float ws[];          // 64*192 floats = 48 KB
    const int tid = threadIdx.x;
    const int rowBase = blockIdx.x * 64;

    // fused weight: ws[k*192 + m*64 + c]
    {
        const float* Wm[3] = {Wq, Wk, Wv};
#pragma unroll
        for (int m = 0; m < 3; m++) {
            const float4* src = (const float4*)Wm[m];
            for (int e = tid; e < 1024; e += 256) {
                int k = e >> 4, c4 = e & 15;
                *(float4*)(ws + k * 192 + m * 64 + c4 * 4) = src[e];
            }
        }
    }
    // x tile (zero-pad past N), stride-65 rows
    for (int e = tid; e < 1024; e += 256) {
        int r = e >> 4, c4 = e & 15;
        float4 v = make_float4(0.f, 0.f, 0.f, 0.f);
        if (rowBase + r < N)
            v = *(const float4*)(x + (size_t)(rowBase + r) * 64 + c4 * 4);
        float* d = xs + r * 65 + c4 * 4;
        d[0] = v.x; d[1] = v.y; d[2] = v.z; d[3] = v.w;
    }
    // p repack (rows of this tile)
    if (tid < 64) {
        int row = rowBase + tid;
        if (row < N)
            g_p4[row] = make_float4(p[row * 3], p[row * 3 + 1], p[row * 3 + 2], 0.f);
    }
    __syncthreads();

    const int tx = tid & 15;      // 16 col groups (4 cols per matrix)
    const int ty = tid >> 4;      // 16 row groups (4 rows each)
    const int r0 = ty * 4;
    const int c0 = tx * 4;

    float2 acc[3][4][2];
    {
        const float* bias[3] = {bq, bk, bv};
#pragma unroll
        for (int m = 0; m < 3; m++) {
            float2 bA = *(const float2*)(bias[m] + c0);
            float2 bB = *(const float2*)(bias[m] + c0 + 2);
#pragma unroll
            for (int r = 0; r < 4; r++) { acc[m][r][0] = bA; acc[m][r][1] = bB; }
        }
    }

#pragma unroll 8
    for (int k = 0; k < 64; k++) {
        float xv[4];
#pragma unroll
        for (int r = 0; r < 4; r++) xv[r] = xs[(r0 + r) * 65 + k];
        const float* wk = ws + k * 192 + c0;
#pragma unroll
        for (int m = 0; m < 3; m++) {
            float4 w4 = *(const float4*)(wk + m * 64);
            float2 wA = make_float2(w4.x, w4.y);
            float2 wB = make_float2(w4.z, w4.w);
#pragma unroll
            for (int r = 0; r < 4; r++) {
                float2 xr = make_float2(xv[r], xv[r]);
                acc[m][r][0] = fma2(xr, wA, acc[m][r][0]);
                acc[m][r][1] = fma2(xr, wB, acc[m][r][1]);
            }
        }
    }

    float* outs[3] = {g_q, g_k, g_v};
#pragma unroll
    for (int m = 0; m < 3; m++) {
#pragma unroll
        for (int r = 0; r < 4; r++) {
            int row = rowBase + r0 + r;
            if (row < N)
                *(float4*)(outs[m] + (size_t)row * 64 + c0) =
                    make_float4(acc[m][r][0].x, acc[m][r][0].y,
                                acc[m][r][1].x, acc[m][r][1].y);
        }
    }
}

// ============================================================================
// Kernel 2: fused attention. 8 points per 128-thread block.
// Stage (lane = 4 channels): single LDG.128 k-gather per neighbor, full
//   BN/pe/ReLU arg -> rv, stored j-major [pt][j][68] (bank-floor 4-phase).
// Phase A (lane = neighbor): a[8] += rv[c]*Wa[c][:], LDS.128 rv + wa bcast.
// Then 8->8 MLP, shfl softmax, channel-parallel coalesced v aggregation.
// ============================================================================
struct __align__(16) K2C {
    float s1[64], bb1[64];
    float ws0[64], ws1[64], ws2[64], wsb[64];  // s1-scaled Wp2 rows + s1*bp2
    float r0[64], r1[64], r2[64], rb[64];      // raw Wp2 rows + bp2 (phase B)
    float wa[512];                             // Wa [64][8]
    float wbm[64];                             // Wb [8][8]
    float s2[8], bb2[8], ba[8], bw[8];
    float wp1[9], bp1v[3], spv[3], bpv[3];
};

#define RV_J_STRIDE 68          // 64 + 4 pad (16B-aligned), bank-floor phases
#define RV_PT_STRIDE 1088       // 16 * 68

__global__ __launch_bounds__(128) void attn_kernel(
    const int* __restrict__ idx,
    const float* __restrict__ Wp1, const float* __restrict__ bp1,
    const float* __restrict__ gp,  const float* __restrict__ bp,
    const float* __restrict__ Wp2, const float* __restrict__ bp2,
    const float* __restrict__ g1,  const float* __restrict__ bb1,
    const float* __restrict__ Wa,  const float* __restrict__ ba,
    const float* __restrict__ g2,  const float* __restrict__ bb2,
    const float* __restrict__ Wb,  const float* __restrict__ bw,
    float* __restrict__ outp, int N)
{
    __shared__ K2C cst;
    __shared__ __align__(16) float4 h_s[8][16];    // post-relu pe hidden
    __shared__ __align__(16) float  w_s[8][16][8]; // softmax weights
    __shared__ int idx_s[8][16];
    extern __shared__ float rv_s[];                // 8 * RV_PT_STRIDE floats

    const int tid = threadIdx.x;
    const float RSQ = rsqrtf(1.f + 1e-5f);

    // ---- constant prep ----
    if (tid < 64) {
        float s1v = g1[tid] * RSQ;
        cst.s1[tid]  = s1v;
        cst.bb1[tid] = bb1[tid];
        float w0 = Wp2[tid], w1 = Wp2[64 + tid], w2 = Wp2[128 + tid], bb = bp2[tid];
        cst.r0[tid] = w0;        cst.r1[tid] = w1;
        cst.r2[tid] = w2;        cst.rb[tid] = bb;
        cst.ws0[tid] = w0 * s1v; cst.ws1[tid] = w1 * s1v;
        cst.ws2[tid] = w2 * s1v; cst.wsb[tid] = bb * s1v;
        cst.wbm[tid] = Wb[tid];
    }
    for (int e = tid; e < 512; e += 128) cst.wa[e] = Wa[e];
    if (tid < 8) {
        cst.s2[tid] = g2[tid] * RSQ;
        cst.bb2[tid] = bb2[tid];
        cst.ba[tid]  = ba[tid];
        cst.bw[tid]  = bw[tid];
    }
    if (tid >= 64 && tid < 73) cst.wp1[tid - 64] = Wp1[tid - 64];
    if (tid >= 80 && tid < 83) {
        int t = tid - 80;
        cst.bp1v[t] = bp1[t]; cst.spv[t] = gp[t] * RSQ; cst.bpv[t] = bp[t];
    }
    __syncthreads();

    const int pt = tid >> 4;          // 0..7
    const int l  = tid & 15;
    const int i0 = blockIdx.x * 8 + pt;
    const int i  = (i0 < N) ? i0 : 0;   // clamp; final store guarded

    // ---- prep: neighbor idx + pe hidden (lane = neighbor) ----
    const int nj = idx[i * 16 + l];
    idx_s[pt][l] = nj;
    {
        float4 pc = g_p4[i];
        float4 pn = g_p4[nj];
        float prx = pn.x - pc.x, pry = pn.y - pc.y, prz = pn.z - pc.z;
        float u0 = cst.bp1v[0] + prx * cst.wp1[0] + pry * cst.wp1[3] + prz * cst.wp1[6];
        float u1 = cst.bp1v[1] + prx * cst.wp1[1] + pry * cst.wp1[4] + prz * cst.wp1[7];
        float u2 = cst.bp1v[2] + prx * cst.wp1[2] + pry * cst.wp1[5] + prz * cst.wp1[8];
        float h0 = fmaxf(fmaf(u0, cst.spv[0], cst.bpv[0]), 0.f);
        float h1 = fmaxf(fmaf(u1, cst.spv[1], cst.bpv[1]), 0.f);
        float h2 = fmaxf(fmaf(u2, cst.spv[2], cst.bpv[2]), 0.f);
        h_s[pt][l] = make_float4(h0, h1, h2, 0.f);
    }
    __syncwarp();

    // ---- stage: lane owns channels 4l..4l+3 across all 16 neighbors ----
    float* rvp = rv_s + pt * RV_PT_STRIDE;
    {
        const int c0 = l * 4;
        float4 s14 = *(const float4*)(cst.s1 + c0);
        float4 xq4;
        {
            float4 q4 = *(const float4*)(g_q + (size_t)i * 64 + c0);
            float4 b4 = *(const float4*)(cst.bb1 + c0);
            xq4.x = fmaf(-q4.x, s14.x, b4.x);
            xq4.y = fmaf(-q4.y, s14.y, b4.y);
            xq4.z = fmaf(-q4.z, s14.z, b4.z);
            xq4.w = fmaf(-q4.w, s14.w, b4.w);
        }
        float4 w04 = *(const float4*)(cst.ws0 + c0);
        float4 w14 = *(const float4*)(cst.ws1 + c0);
        float4 w24 = *(const float4*)(cst.ws2 + c0);
        float4 wb4 = *(const float4*)(cst.wsb + c0);

#pragma unroll 4
        for (int jj = 0; jj < 16; jj++) {
            int nb    = idx_s[pt][jj];
            float4 h4 = h_s[pt][jj];
            float4 kv = *(const float4*)(g_k + (size_t)nb * 64 + c0);
            float2 hx = make_float2(h4.x, h4.x);
            float2 hy = make_float2(h4.y, h4.y);
            float2 hz = make_float2(h4.z, h4.z);
            float2 pe01 = fma2(hx, make_float2(w04.x, w04.y),
                          fma2(hy, make_float2(w14.x, w14.y),
                          fma2(hz, make_float2(w24.x, w24.y), make_float2(wb4.x, wb4.y))));
            float2 pe23 = fma2(hx, make_float2(w04.z, w04.w),
                          fma2(hy, make_float2(w14.z, w14.w),
                          fma2(hz, make_float2(w24.z, w24.w), make_float2(wb4.z, wb4.w))));
            float2 a01 = fma2(make_float2(kv.x, kv.y), make_float2(s14.x, s14.y),
                              add2(make_float2(xq4.x, xq4.y), pe01));
            float2 a23 = fma2(make_float2(kv.z, kv.w), make_float2(s14.z, s14.w),
                              add2(make_float2(xq4.z, xq4.w), pe23));
            *(float4*)(rvp + jj * RV_J_STRIDE + c0) =
                make_float4(fmaxf(a01.x, 0.f), fmaxf(a01.y, 0.f),
                            fmaxf(a23.x, 0.f), fmaxf(a23.y, 0.f));
        }
    }
    __syncwarp();

    // ---- phase A: lane = neighbor; a[8] = ba + sum_c rv[c] * Wa[c][:] ----
    float2 a2[4];
#pragma unroll
    for (int q = 0; q < 4; q++) a2[q] = *(const float2*)(cst.ba + q * 2);
    {
        const float* rvj = rvp + l * RV_J_STRIDE;
#pragma unroll 4
        for (int c4 = 0; c4 < 16; c4++) {
            float4 rv4 = *(const float4*)(rvj + c4 * 4);
            float rvv[4] = {rv4.x, rv4.y, rv4.z, rv4.w};
#pragma unroll
            for (int ii = 0; ii < 4; ii++) {
                const float2* war = (const float2*)(cst.wa + (c4 * 4 + ii) * 8);
                float2 rr = make_float2(rvv[ii], rvv[ii]);
                a2[0] = fma2(rr, war[0], a2[0]);
                a2[1] = fma2(rr, war[1], a2[1]);
                a2[2] = fma2(rr, war[2], a2[2]);
                a2[3] = fma2(rr, war[3], a2[3]);
            }
        }
    }

    // ---- second MLP (8 -> 8) ----
    float2 b2[4];
#pragma unroll
    for (int q = 0; q < 4; q++) b2[q] = *(const float2*)(cst.bw + q * 2);
#pragma unroll
    for (int m = 0; m < 8; m++) {
        float avm = (m & 1) ? a2[m >> 1].y : a2[m >> 1].x;
        float t = fmaxf(fmaf(avm, cst.s2[m], cst.bb2[m]), 0.f);
        float2 tt = make_float2(t, t);
        const float2* wr = (const float2*)(cst.wbm + m * 8);
        b2[0] = fma2(tt, wr[0], b2[0]);
        b2[1] = fma2(tt, wr[1], b2[1]);
        b2[2] = fma2(tt, wr[2], b2[2]);
        b2[3] = fma2(tt, wr[3], b2[3]);
    }

    // ---- softmax over 16 neighbors (xor-shfl within 16-lane group) ----
    float w8[8];
#pragma unroll
    for (int m = 0; m < 8; m++) {
        float v = (m & 1) ? b2[m >> 1].y : b2[m >> 1].x;
        float mx = v;
#pragma unroll
        for (int off = 8; off >= 1; off >>= 1)
            mx = fmaxf(mx, __shfl_xor_sync(0xffffffffu, mx, off));
        float e = __expf(v - mx);
        float s = e;
#pragma unroll
        for (int off = 8; off >= 1; off >>= 1)
            s += __shfl_xor_sync(0xffffffffu, s, off);
        w8[m] = __fdividef(e, s);
    }
    *(float4*)&w_s[pt][l][0] = make_float4(w8[0], w8[1], w8[2], w8[3]);
    *(float4*)&w_s[pt][l][4] = make_float4(w8[4], w8[5], w8[6], w8[7]);
    __syncwarp();

    // ---- phase B: channel-parallel aggregation (coalesced v gather) ----
    const int c0 = l * 4;
    const int m0 = (l & 1) * 4;
    float4 rr0 = *(const float4*)(cst.r0 + c0);
    float4 rr1 = *(const float4*)(cst.r1 + c0);
    float4 rr2 = *(const float4*)(cst.r2 + c0);
    float4 rrb = *(const float4*)(cst.rb + c0);
    float2 acc01 = make_float2(0.f, 0.f), acc23 = make_float2(0.f, 0.f);
#pragma unroll
    for (int jj = 0; jj < 16; jj++) {
        int nb    = idx_s[pt][jj];
        float4 h4 = h_s[pt][jj];
        float4 wv = *(const float4*)&w_s[pt][jj][m0];
        float4 v4 = *(const float4*)(g_v + (size_t)nb * 64 + c0);
        float2 hx = make_float2(h4.x, h4.x);
        float2 hy = make_float2(h4.y, h4.y);
        float2 hz = make_float2(h4.z, h4.z);
        float2 pe01 = fma2(hx, make_float2(rr0.x, rr0.y),
                      fma2(hy, make_float2(rr1.x, rr1.y),
                      fma2(hz, make_float2(rr2.x, rr2.y), make_float2(rrb.x, rrb.y))));
        float2 pe23 = fma2(hx, make_float2(rr0.z, rr0.w),
                      fma2(hy, make_float2(rr1.z, rr1.w),
                      fma2(hz, make_float2(rr2.z, rr2.w), make_float2(rrb.z, rrb.w))));
        acc01 = fma2(add2(make_float2(v4.x, v4.y), pe01), make_float2(wv.x, wv.y), acc01);
        acc23 = fma2(add2(make_float2(v4.z, v4.w), pe23), make_float2(wv.z, wv.w), acc23);
    }
    if (i0 < N)
        *(float4*)(outp + (size_t)i0 * 64 + c0) =
            make_float4(acc01.x, acc01.y, acc23.x, acc23.y);
}

// ============================================================================
extern "C" void kernel_launch(void* const* d_in, const int* in_sizes, int n_in,
                              void* d_out, int out_size) {
    const float* p   = (const float*)d_in[0];
    const float* x   = (const float*)d_in[1];
    const int*   idx = (const int*)d_in[2];
    const float* Wq  = (const float*)d_in[3];  const float* bq  = (const float*)d_in[4];
    const float* Wk  = (const float*)d_in[5];  const float* bk  = (const float*)d_in[6];
    const float* Wv  = (const float*)d_in[7];  const float* bv  = (const float*)d_in[8];
    const float* Wp1 = (const float*)d_in[9];  const float* bp1 = (const float*)d_in[10];
    const float* gp  = (const float*)d_in[11]; const float* bp  = (const float*)d_in[12];
    const float* Wp2 = (const float*)d_in[13]; const float* bp2 = (const float*)d_in[14];
    const float* g1  = (const float*)d_in[15]; const float* bb1 = (const float*)d_in[16];
    const float* Wa  = (const float*)d_in[17]; const float* ba  = (const float*)d_in[18];
    const float* g2  = (const float*)d_in[19]; const float* bb2 = (const float*)d_in[20];
    const float* Wb  = (const float*)d_in[21]; const float* bw  = (const float*)d_in[22];

    int N = in_sizes[0] / 3;
    if (N > MAXN) N = MAXN;  // scratch bound (problem shape is N=100000)

    const int qkv_dyn  = 64 * 192 * (int)sizeof(float);           // 49152
    const int attn_dyn = 8 * RV_PT_STRIDE * (int)sizeof(float);   // 34816
    cudaFuncSetAttribute(qkv_kernel,  cudaFuncAttributeMaxDynamicSharedMemorySize, qkv_dyn);
    cudaFuncSetAttribute(attn_kernel, cudaFuncAttributeMaxDynamicSharedMemorySize, attn_dyn);

    qkv_kernel<<<(N + 63) / 64, 256, qkv_dyn>>>(x, p, Wq, bq, Wk, bk, Wv, bv, N);

    attn_kernel<<<(N + 7) / 8, 128, attn_dyn>>>(idx, Wp1, bp1, gp, bp, Wp2, bp2,
                                                g1, bb1, Wa, ba, g2, bb2, Wb, bw,
                                                (float*)d_out, N);
}

// round 5
// speedup vs baseline: 1.4715x; 1.1014x over previous
#include <cuda_runtime.h>
#include <cstdint>
#include <cstddef>

#define MAXN 131072

// scratch (device globals: no allocation allowed)
__device__ float g_q[MAXN * 64];
__device__ float g_k[MAXN * 64];
__device__ float g_v[MAXN * 64];
__device__ float4 g_p4[MAXN];

// ---- packed fp32x2 ops (sm_103a FFMA2 path) ----
__device__ __forceinline__ float2 fma2(float2 a, float2 b, float2 c) {
    float2 d;
    asm("fma.rn.f32x2 %0, %1, %2, %3;"
        : "=l"(*(unsigned long long*)&d)
        : "l"(*(unsigned long long*)&a),
          "l"(*(unsigned long long*)&b),
          "l"(*(unsigned long long*)&c));
    return d;
}
__device__ __forceinline__ float2 add2(float2 a, float2 b) {
    float2 d;
    asm("add.rn.f32x2 %0, %1, %2;"
        : "=l"(*(unsigned long long*)&d)
        : "l"(*(unsigned long long*)&a),
          "l"(*(unsigned long long*)&b));
    return d;
}

// ============================================================================
// Kernel 1: fused q/k/v = x @ [Wq|Wk|Wv] + b, plus p -> g_p4 repack.
// ============================================================================
__global__ __launch_bounds__(256) void qkv_kernel(
    const float* __restrict__ x, const float* __restrict__ p,
    const float* __restrict__ Wq, const float* __restrict__ bq,
    const float* __restrict__ Wk, const float* __restrict__ bk,
    const float* __restrict__ Wv, const float* __restrict__ bv,
    int N)
{
    __shared__ float xs[64 * 65];          // 16.6 KB
    extern __shared__ float ws[];          // 64*192 floats = 48 KB
    const int tid = threadIdx.x;
    const int rowBase = blockIdx.x * 64;

    // fused weight: ws[k*192 + m*64 + c]
    {
        const float* Wm[3] = {Wq, Wk, Wv};
#pragma unroll
        for (int m = 0; m < 3; m++) {
            const float4* src = (const float4*)Wm[m];
            for (int e = tid; e < 1024; e += 256) {
                int k = e >> 4, c4 = e & 15;
                *(float4*)(ws + k * 192 + m * 64 + c4 * 4) = src[e];
            }
        }
    }
    // x tile (zero-pad past N), stride-65 rows
    for (int e = tid; e < 1024; e += 256) {
        int r = e >> 4, c4 = e & 15;
        float4 v = make_float4(0.f, 0.f, 0.f, 0.f);
        if (rowBase + r < N)
            v = *(const float4*)(x + (size_t)(rowBase + r) * 64 + c4 * 4);
        float* d = xs + r * 65 + c4 * 4;
        d[0] = v.x; d[1] = v.y; d[2] = v.z; d[3] = v.w;
    }
    // p repack (rows of this tile)
    if (tid < 64) {
        int row = rowBase + tid;
        if (row < N)
            g_p4[row] = make_float4(p[row * 3], p[row * 3 + 1], p[row * 3 + 2], 0.f);
    }
    __syncthreads();

    const int tx = tid & 15;      // 16 col groups (4 cols per matrix)
    const int ty = tid >> 4;      // 16 row groups (4 rows each)
    const int r0 = ty * 4;
    const int c0 = tx * 4;

    float2 acc[3][4][2];
    {
        const float* bias[3] = {bq, bk, bv};
#pragma unroll
        for (int m = 0; m < 3; m++) {
            float2 bA = *(const float2*)(bias[m] + c0);
            float2 bB = *(const float2*)(bias[m] + c0 + 2);
#pragma unroll
            for (int r = 0; r < 4; r++) { acc[m][r][0] = bA; acc[m][r][1] = bB; }
        }
    }

#pragma unroll 8
    for (int k = 0; k < 64; k++) {
        float xv[4];
#pragma unroll
        for (int r = 0; r < 4; r++) xv[r] = xs[(r0 + r) * 65 + k];
        const float* wk = ws + k * 192 + c0;
#pragma unroll
        for (int m = 0; m < 3; m++) {
            float4 w4 = *(const float4*)(wk + m * 64);
            float2 wA = make_float2(w4.x, w4.y);
            float2 wB = make_float2(w4.z, w4.w);
#pragma unroll
            for (int r = 0; r < 4; r++) {
                float2 xr = make_float2(xv[r], xv[r]);
                acc[m][r][0] = fma2(xr, wA, acc[m][r][0]);
                acc[m][r][1] = fma2(xr, wB, acc[m][r][1]);
            }
        }
    }

    float* outs[3] = {g_q, g_k, g_v};
#pragma unroll
    for (int m = 0; m < 3; m++) {
#pragma unroll
        for (int r = 0; r < 4; r++) {
            int row = rowBase + r0 + r;
            if (row < N)
                *(float4*)(outs[m] + (size_t)row * 64 + c0) =
                    make_float4(acc[m][r][0].x, acc[m][r][0].y,
                                acc[m][r][1].x, acc[m][r][1].y);
        }
    }
}

// ============================================================================
// Kernel 2: fused attention. 8 points per 128-thread block; rv chunked by 32
// channels (halves smem -> ~7 blocks/SM); wa read via LDS.128 (2/channel);
// softmax weights overlay each point's own dead rv region.
// ============================================================================
struct __align__(16) K2C {
    float s1[64], bb1[64];
    float ws0[64], ws1[64], ws2[64], wsb[64];  // s1-scaled Wp2 rows + s1*bp2
    float r0[64], r1[64], r2[64], rb[64];      // raw Wp2 rows + bp2 (phase B)
    float wa[512];                             // Wa [64][8] (rows 32B-aligned)
    float wbm[64];                             // Wb [8][8]
    float s2[8], bb2[8], ba[8], bw[8];
    float wp1[9], bp1v[3], spv[3], bpv[3];
};

#define RV_J_STRIDE 36          // 32 ch + 4 pad
#define RV_PT_STRIDE 576        // 16 * 36
#define W_J_STRIDE 12           // softmax weight row (8 + 4 pad), 48B

__global__ __launch_bounds__(128, 7) void attn_kernel(
    const int* __restrict__ idx,
    const float* __restrict__ Wp1, const float* __restrict__ bp1,
    const float* __restrict__ gp,  const float* __restrict__ bp,
    const float* __restrict__ Wp2, const float* __restrict__ bp2,
    const float* __restrict__ g1,  const float* __restrict__ bb1,
    const float* __restrict__ Wa,  const float* __restrict__ ba,
    const float* __restrict__ g2,  const float* __restrict__ bb2,
    const float* __restrict__ Wb,  const float* __restrict__ bw,
    float* __restrict__ outp, int N)
{
    __shared__ K2C cst;
    __shared__ __align__(16) float4 h_s[8][16];    // post-relu pe hidden
    __shared__ int idx_s[8][16];
    extern __shared__ float rv_s[];                // 8 * RV_PT_STRIDE floats

    const int tid = threadIdx.x;
    const float RSQ = rsqrtf(1.f + 1e-5f);

    // ---- constant prep ----
    if (tid < 64) {
        float s1v = g1[tid] * RSQ;
        cst.s1[tid]  = s1v;
        cst.bb1[tid] = bb1[tid];
        float w0 = Wp2[tid], w1 = Wp2[64 + tid], w2 = Wp2[128 + tid], bb = bp2[tid];
        cst.r0[tid] = w0;        cst.r1[tid] = w1;
        cst.r2[tid] = w2;        cst.rb[tid] = bb;
        cst.ws0[tid] = w0 * s1v; cst.ws1[tid] = w1 * s1v;
        cst.ws2[tid] = w2 * s1v; cst.wsb[tid] = bb * s1v;
        cst.wbm[tid] = Wb[tid];
    }
    for (int e = tid; e < 512; e += 128) cst.wa[e] = Wa[e];
    if (tid < 8) {
        cst.s2[tid] = g2[tid] * RSQ;
        cst.bb2[tid] = bb2[tid];
        cst.ba[tid]  = ba[tid];
        cst.bw[tid]  = bw[tid];
    }
    if (tid >= 64 && tid < 73) cst.wp1[tid - 64] = Wp1[tid - 64];
    if (tid >= 80 && tid < 83) {
        int t = tid - 80;
        cst.bp1v[t] = bp1[t]; cst.spv[t] = gp[t] * RSQ; cst.bpv[t] = bp[t];
    }
    __syncthreads();

    const int pt = tid >> 4;          // 0..7
    const int l  = tid & 15;
    const int i0 = blockIdx.x * 8 + pt;
    const int i  = (i0 < N) ? i0 : 0;   // clamp; final store guarded

    // ---- prep: neighbor idx + pe hidden (lane = neighbor) ----
    const int nj = idx[i * 16 + l];
    idx_s[pt][l] = nj;
    {
        float4 pc = g_p4[i];
        float4 pn = g_p4[nj];
        float prx = pn.x - pc.x, pry = pn.y - pc.y, prz = pn.z - pc.z;
        float u0 = cst.bp1v[0] + prx * cst.wp1[0] + pry * cst.wp1[3] + prz * cst.wp1[6];
        float u1 = cst.bp1v[1] + prx * cst.wp1[1] + pry * cst.wp1[4] + prz * cst.wp1[7];
        float u2 = cst.bp1v[2] + prx * cst.wp1[2] + pry * cst.wp1[5] + prz * cst.wp1[8];
        float h0 = fmaxf(fmaf(u0, cst.spv[0], cst.bpv[0]), 0.f);
        float h1 = fmaxf(fmaf(u1, cst.spv[1], cst.bpv[1]), 0.f);
        float h2 = fmaxf(fmaf(u2, cst.spv[2], cst.bpv[2]), 0.f);
        h_s[pt][l] = make_float4(h0, h1, h2, 0.f);
    }
    __syncwarp();

    float* rvp = rv_s + pt * RV_PT_STRIDE;

    float2 a2[4];
#pragma unroll
    for (int q = 0; q < 4; q++) a2[q] = *(const float2*)(cst.ba + q * 2);

    // ---- chunked stage + phase A (2 chunks of 32 channels) ----
#pragma unroll
    for (int cb = 0; cb < 64; cb += 32) {
        // stage: lane owns channels (cb+2l, cb+2l+1)
        const int c0 = cb + l * 2;
        float2 s12 = *(const float2*)(cst.s1 + c0);
        float2 xq2;
        {
            float2 q2 = *(const float2*)(g_q + (size_t)i * 64 + c0);
            float2 b2v = *(const float2*)(cst.bb1 + c0);
            xq2.x = fmaf(-q2.x, s12.x, b2v.x);
            xq2.y = fmaf(-q2.y, s12.y, b2v.y);
        }
        float2 w02 = *(const float2*)(cst.ws0 + c0);
        float2 w12 = *(const float2*)(cst.ws1 + c0);
        float2 w22 = *(const float2*)(cst.ws2 + c0);
        float2 wb2 = *(const float2*)(cst.wsb + c0);

#pragma unroll 4
        for (int jj = 0; jj < 16; jj++) {
            int nb    = idx_s[pt][jj];
            float4 h4 = h_s[pt][jj];
            float2 kv = *(const float2*)(g_k + (size_t)nb * 64 + c0);
            float2 pe = fma2(make_float2(h4.x, h4.x), w02,
                        fma2(make_float2(h4.y, h4.y), w12,
                        fma2(make_float2(h4.z, h4.z), w22, wb2)));
            float2 arg = fma2(kv, s12, add2(xq2, pe));
            *(float2*)(rvp + jj * RV_J_STRIDE + l * 2) =
                make_float2(fmaxf(arg.x, 0.f), fmaxf(arg.y, 0.f));
        }
        __syncwarp();

        // phase A partial: lane = neighbor l; channels cb..cb+31
        {
            const float* rvj = rvp + l * RV_J_STRIDE;
#pragma unroll
            for (int c4 = 0; c4 < 8; c4++) {
                float4 rv4 = *(const float4*)(rvj + c4 * 4);
                float rvv[4] = {rv4.x, rv4.y, rv4.z, rv4.w};
#pragma unroll
                for (int ii = 0; ii < 4; ii++) {
                    const float* war = cst.wa + (cb + c4 * 4 + ii) * 8;
                    float4 wa0 = *(const float4*)(war);
                    float4 wa1 = *(const float4*)(war + 4);
                    float2 rr = make_float2(rvv[ii], rvv[ii]);
                    a2[0] = fma2(rr, make_float2(wa0.x, wa0.y), a2[0]);
                    a2[1] = fma2(rr, make_float2(wa0.z, wa0.w), a2[1]);
                    a2[2] = fma2(rr, make_float2(wa1.x, wa1.y), a2[2]);
                    a2[3] = fma2(rr, make_float2(wa1.z, wa1.w), a2[3]);
                }
            }
        }
        __syncwarp();
    }

    // ---- second MLP (8 -> 8) ----
    float2 b2[4];
#pragma unroll
    for (int q = 0; q < 4; q++) b2[q] = *(const float2*)(cst.bw + q * 2);
#pragma unroll
    for (int m = 0; m < 8; m++) {
        float avm = (m & 1) ? a2[m >> 1].y : a2[m >> 1].x;
        float t = fmaxf(fmaf(avm, cst.s2[m], cst.bb2[m]), 0.f);
        float2 tt = make_float2(t, t);
        const float2* wr = (const float2*)(cst.wbm + m * 8);
        b2[0] = fma2(tt, wr[0], b2[0]);
        b2[1] = fma2(tt, wr[1], b2[1]);
        b2[2] = fma2(tt, wr[2], b2[2]);
        b2[3] = fma2(tt, wr[3], b2[3]);
    }

    // ---- softmax over 16 neighbors (xor-shfl within 16-lane group) ----
    float w8[8];
#pragma unroll
    for (int m = 0; m < 8; m++) {
        float v = (m & 1) ? b2[m >> 1].y : b2[m >> 1].x;
        float mx = v;
#pragma unroll
        for (int off = 8; off >= 1; off >>= 1)
            mx = fmaxf(mx, __shfl_xor_sync(0xffffffffu, mx, off));
        float e = __expf(v - mx);
        float s = e;
#pragma unroll
        for (int off = 8; off >= 1; off >>= 1)
            s += __shfl_xor_sync(0xffffffffu, s, off);
        w8[m] = __fdividef(e, s);
    }
    // overlay softmax weights into this point's own (dead) rv region
    float* wp = rvp + l * W_J_STRIDE;
    *(float4*)(wp)     = make_float4(w8[0], w8[1], w8[2], w8[3]);
    *(float4*)(wp + 4) = make_float4(w8[4], w8[5], w8[6], w8[7]);
    __syncwarp();

    // ---- phase B: channel-parallel aggregation (coalesced v gather) ----
    const int c0 = l * 4;
    const int m0 = (l & 1) * 4;
    float4 rr0 = *(const float4*)(cst.r0 + c0);
    float4 rr1 = *(const float4*)(cst.r1 + c0);
    float4 rr2 = *(const float4*)(cst.r2 + c0);
    float4 rrb = *(const float4*)(cst.rb + c0);
    float2 acc01 = make_float2(0.f, 0.f), acc23 = make_float2(0.f, 0.f);
#pragma unroll 4
    for (int jj = 0; jj < 16; jj++) {
        int nb    = idx_s[pt][jj];
        float4 h4 = h_s[pt][jj];
        float4 wv = *(const float4*)(rvp + jj * W_J_STRIDE + m0);
        float4 v4 = *(const float4*)(g_v + (size_t)nb * 64 + c0);
        float2 hx = make_float2(h4.x, h4.x);
        float2 hy = make_float2(h4.y, h4.y);
        float2 hz = make_float2(h4.z, h4.z);
        float2 pe01 = fma2(hx, make_float2(rr0.x, rr0.y),
                      fma2(hy, make_float2(rr1.x, rr1.y),
                      fma2(hz, make_float2(rr2.x, rr2.y), make_float2(rrb.x, rrb.y))));
        float2 pe23 = fma2(hx, make_float2(rr0.z, rr0.w),
                      fma2(hy, make_float2(rr1.z, rr1.w),
                      fma2(hz, make_float2(rr2.z, rr2.w), make_float2(rrb.z, rrb.w))));
        acc01 = fma2(add2(make_float2(v4.x, v4.y), pe01), make_float2(wv.x, wv.y), acc01);
        acc23 = fma2(add2(make_float2(v4.z, v4.w), pe23), make_float2(wv.z, wv.w), acc23);
    }
    if (i0 < N)
        *(float4*)(outp + (size_t)i0 * 64 + c0) =
            make_float4(acc01.x, acc01.y, acc23.x, acc23.y);
}

// ============================================================================
extern "C" void kernel_launch(void* const* d_in, const int* in_sizes, int n_in,
                              void* d_out, int out_size) {
    const float* p   = (const float*)d_in[0];
    const float* x   = (const float*)d_in[1];
    const int*   idx = (const int*)d_in[2];
    const float* Wq  = (const float*)d_in[3];  const float* bq  = (const float*)d_in[4];
    const float* Wk  = (const float*)d_in[5];  const float* bk  = (const float*)d_in[6];
    const float* Wv  = (const float*)d_in[7];  const float* bv  = (const float*)d_in[8];
    const float* Wp1 = (const float*)d_in[9];  const float* bp1 = (const float*)d_in[10];
    const float* gp  = (const float*)d_in[11]; const float* bp  = (const float*)d_in[12];
    const float* Wp2 = (const float*)d_in[13]; const float* bp2 = (const float*)d_in[14];
    const float* g1  = (const float*)d_in[15]; const float* bb1 = (const float*)d_in[16];
    const float* Wa  = (const float*)d_in[17]; const float* ba  = (const float*)d_in[18];
    const float* g2  = (const float*)d_in[19]; const float* bb2 = (const float*)d_in[20];
    const float* Wb  = (const float*)d_in[21]; const float* bw  = (const float*)d_in[22];

    int N = in_sizes[0] / 3;
    if (N > MAXN) N = MAXN;  // scratch bound (problem shape is N=100000)

    const int qkv_dyn  = 64 * 192 * (int)sizeof(float);           // 49152
    const int attn_dyn = 8 * RV_PT_STRIDE * (int)sizeof(float);   // 18432
    cudaFuncSetAttribute(qkv_kernel,  cudaFuncAttributeMaxDynamicSharedMemorySize, qkv_dyn);
    cudaFuncSetAttribute(attn_kernel, cudaFuncAttributeMaxDynamicSharedMemorySize, attn_dyn);

    qkv_kernel<<<(N + 63) / 64, 256, qkv_dyn>>>(x, p, Wq, bq, Wk, bk, Wv, bv, N);

    attn_kernel<<<(N + 7) / 8, 128, attn_dyn>>>(idx, Wp1, bp1, gp, bp, Wp2, bp2,
                                                g1, bb1, Wa, ba, g2, bb2, Wb, bw,
                                                (float*)d_out, N);
}

// round 6
// speedup vs baseline: 1.5529x; 1.0554x over previous
#include <cuda_runtime.h>
#include <cstdint>
#include <cstddef>

#define MAXN 131072

// scratch (device globals: no allocation allowed)
__device__ float g_q[MAXN * 64];
__device__ float g_k[MAXN * 64];
__device__ float g_v[MAXN * 64];
__device__ float4 g_p4[MAXN];

// ---- packed fp32x2 ops (sm_103a FFMA2 path) ----
__device__ __forceinline__ float2 fma2(float2 a, float2 b, float2 c) {
    float2 d;
    asm("fma.rn.f32x2 %0, %1, %2, %3;"
        : "=l"(*(unsigned long long*)&d)
        : "l"(*(unsigned long long*)&a),
          "l"(*(unsigned long long*)&b),
          "l"(*(unsigned long long*)&c));
    return d;
}
__device__ __forceinline__ float2 add2(float2 a, float2 b) {
    float2 d;
    asm("add.rn.f32x2 %0, %1, %2;"
        : "=l"(*(unsigned long long*)&d)
        : "l"(*(unsigned long long*)&a),
          "l"(*(unsigned long long*)&b));
    return d;
}

// ============================================================================
// Kernel 1: fused q/k/v = x @ [Wq|Wk|Wv] + b, plus p -> g_p4 repack.
// ============================================================================
__global__ __launch_bounds__(256) void qkv_kernel(
    const float* __restrict__ x, const float* __restrict__ p,
    const float* __restrict__ Wq, const float* __restrict__ bq,
    const float* __restrict__ Wk, const float* __restrict__ bk,
    const float* __restrict__ Wv, const float* __restrict__ bv,
    int N)
{
    __shared__ float xs[64 * 65];          // 16.6 KB
    extern __shared__ float ws[];          // 64*192 floats = 48 KB
    const int tid = threadIdx.x;
    const int rowBase = blockIdx.x * 64;

    // fused weight: ws[k*192 + m*64 + c]
    {
        const float* Wm[3] = {Wq, Wk, Wv};
#pragma unroll
        for (int m = 0; m < 3; m++) {
            const float4* src = (const float4*)Wm[m];
            for (int e = tid; e < 1024; e += 256) {
                int k = e >> 4, c4 = e & 15;
                *(float4*)(ws + k * 192 + m * 64 + c4 * 4) = src[e];
            }
        }
    }
    // x tile (zero-pad past N), stride-65 rows
    for (int e = tid; e < 1024; e += 256) {
        int r = e >> 4, c4 = e & 15;
        float4 v = make_float4(0.f, 0.f, 0.f, 0.f);
        if (rowBase + r < N)
            v = *(const float4*)(x + (size_t)(rowBase + r) * 64 + c4 * 4);
        float* d = xs + r * 65 + c4 * 4;
        d[0] = v.x; d[1] = v.y; d[2] = v.z; d[3] = v.w;
    }
    // p repack (rows of this tile)
    if (tid < 64) {
        int row = rowBase + tid;
        if (row < N)
            g_p4[row] = make_float4(p[row * 3], p[row * 3 + 1], p[row * 3 + 2], 0.f);
    }
    __syncthreads();

    const int tx = tid & 15;      // 16 col groups (4 cols per matrix)
    const int ty = tid >> 4;      // 16 row groups (4 rows each)
    const int r0 = ty * 4;
    const int c0 = tx * 4;

    float2 acc[3][4][2];
    {
        const float* bias[3] = {bq, bk, bv};
#pragma unroll
        for (int m = 0; m < 3; m++) {
            float2 bA = *(const float2*)(bias[m] + c0);
            float2 bB = *(const float2*)(bias[m] + c0 + 2);
#pragma unroll
            for (int r = 0; r < 4; r++) { acc[m][r][0] = bA; acc[m][r][1] = bB; }
        }
    }

#pragma unroll 8
    for (int k = 0; k < 64; k++) {
        float xv[4];
#pragma unroll
        for (int r = 0; r < 4; r++) xv[r] = xs[(r0 + r) * 65 + k];
        const float* wk = ws + k * 192 + c0;
#pragma unroll
        for (int m = 0; m < 3; m++) {
            float4 w4 = *(const float4*)(wk + m * 64);
            float2 wA = make_float2(w4.x, w4.y);
            float2 wB = make_float2(w4.z, w4.w);
#pragma unroll
            for (int r = 0; r < 4; r++) {
                float2 xr = make_float2(xv[r], xv[r]);
                acc[m][r][0] = fma2(xr, wA, acc[m][r][0]);
                acc[m][r][1] = fma2(xr, wB, acc[m][r][1]);
            }
        }
    }

    float* outs[3] = {g_q, g_k, g_v};
#pragma unroll
    for (int m = 0; m < 3; m++) {
#pragma unroll
        for (int r = 0; r < 4; r++) {
            int row = rowBase + r0 + r;
            if (row < N)
                *(float4*)(outs[m] + (size_t)row * 64 + c0) =
                    make_float4(acc[m][r][0].x, acc[m][r][0].y,
                                acc[m][r][1].x, acc[m][r][1].y);
        }
    }
}

// ============================================================================
// Kernel 2: fused attention. 8 points per 128-thread block.
// Neighbor index + pe-hidden live in lane-jj registers; stage and phase B
// fetch them via width-16 shuffles (zero L1 wavefronts). rv chunked by 32
// channels; softmax weights overlay dead rv region.
// ============================================================================
struct __align__(16) K2C {
    float s1[64], bb1[64];
    float ws0[64], ws1[64], ws2[64], wsb[64];  // s1-scaled Wp2 rows + s1*bp2
    float r0[64], r1[64], r2[64], rb[64];      // raw Wp2 rows + bp2 (phase B)
    float wa[512];                             // Wa [64][8] (rows 32B-aligned)
    float wbm[64];                             // Wb [8][8]
    float s2[8], bb2[8], ba[8], bw[8];
    float wp1[9], bp1v[3], spv[3], bpv[3];
};

#define RV_J_STRIDE 36          // 32 ch + 4 pad
#define RV_PT_STRIDE 576        // 16 * 36
#define W_J_STRIDE 12           // softmax weight row (8 + 4 pad), 48B

__global__ __launch_bounds__(128, 8) void attn_kernel(
    const int* __restrict__ idx,
    const float* __restrict__ Wp1, const float* __restrict__ bp1,
    const float* __restrict__ gp,  const float* __restrict__ bp,
    const float* __restrict__ Wp2, const float* __restrict__ bp2,
    const float* __restrict__ g1,  const float* __restrict__ bb1,
    const float* __restrict__ Wa,  const float* __restrict__ ba,
    const float* __restrict__ g2,  const float* __restrict__ bb2,
    const float* __restrict__ Wb,  const float* __restrict__ bw,
    float* __restrict__ outp, int N)
{
    __shared__ K2C cst;
    extern __shared__ float rv_s[];                // 8 * RV_PT_STRIDE floats

    const int tid = threadIdx.x;
    const float RSQ = rsqrtf(1.f + 1e-5f);

    // ---- constant prep ----
    if (tid < 64) {
        float s1v = g1[tid] * RSQ;
        cst.s1[tid]  = s1v;
        cst.bb1[tid] = bb1[tid];
        float w0 = Wp2[tid], w1 = Wp2[64 + tid], w2 = Wp2[128 + tid], bb = bp2[tid];
        cst.r0[tid] = w0;        cst.r1[tid] = w1;
        cst.r2[tid] = w2;        cst.rb[tid] = bb;
        cst.ws0[tid] = w0 * s1v; cst.ws1[tid] = w1 * s1v;
        cst.ws2[tid] = w2 * s1v; cst.wsb[tid] = bb * s1v;
        cst.wbm[tid] = Wb[tid];
    }
    for (int e = tid; e < 512; e += 128) cst.wa[e] = Wa[e];
    if (tid < 8) {
        cst.s2[tid] = g2[tid] * RSQ;
        cst.bb2[tid] = bb2[tid];
        cst.ba[tid]  = ba[tid];
        cst.bw[tid]  = bw[tid];
    }
    if (tid >= 64 && tid < 73) cst.wp1[tid - 64] = Wp1[tid - 64];
    if (tid >= 80 && tid < 83) {
        int t = tid - 80;
        cst.bp1v[t] = bp1[t]; cst.spv[t] = gp[t] * RSQ; cst.bpv[t] = bp[t];
    }
    __syncthreads();

    const int pt = tid >> 4;          // 0..7
    const int l  = tid & 15;
    const int i0 = blockIdx.x * 8 + pt;
    const int i  = (i0 < N) ? i0 : 0;   // clamp; final store guarded

    // ---- prep (lane = neighbor l): nj + pe hidden, kept in registers ----
    const int nj = idx[i * 16 + l];
    float h0, h1, h2;
    {
        float4 pc = g_p4[i];
        float4 pn = g_p4[nj];
        float prx = pn.x - pc.x, pry = pn.y - pc.y, prz = pn.z - pc.z;
        float u0 = cst.bp1v[0] + prx * cst.wp1[0] + pry * cst.wp1[3] + prz * cst.wp1[6];
        float u1 = cst.bp1v[1] + prx * cst.wp1[1] + pry * cst.wp1[4] + prz * cst.wp1[7];
        float u2 = cst.bp1v[2] + prx * cst.wp1[2] + pry * cst.wp1[5] + prz * cst.wp1[8];
        h0 = fmaxf(fmaf(u0, cst.spv[0], cst.bpv[0]), 0.f);
        h1 = fmaxf(fmaf(u1, cst.spv[1], cst.bpv[1]), 0.f);
        h2 = fmaxf(fmaf(u2, cst.spv[2], cst.bpv[2]), 0.f);
    }

    float* rvp = rv_s + pt * RV_PT_STRIDE;

    float2 a2[4];
#pragma unroll
    for (int q = 0; q < 4; q++) a2[q] = *(const float2*)(cst.ba + q * 2);

    // ---- chunked stage + phase A (2 chunks of 32 channels) ----
#pragma unroll
    for (int cb = 0; cb < 64; cb += 32) {
        // stage: lane owns channels (cb+2l, cb+2l+1)
        const int c0 = cb + l * 2;
        float2 s12 = *(const float2*)(cst.s1 + c0);
        float2 xq2;
        {
            float2 q2 = *(const float2*)(g_q + (size_t)i * 64 + c0);
            float2 b2v = *(const float2*)(cst.bb1 + c0);
            xq2.x = fmaf(-q2.x, s12.x, b2v.x);
            xq2.y = fmaf(-q2.y, s12.y, b2v.y);
        }
        float2 w02 = *(const float2*)(cst.ws0 + c0);
        float2 w12 = *(const float2*)(cst.ws1 + c0);
        float2 w22 = *(const float2*)(cst.ws2 + c0);
        float2 wb2 = *(const float2*)(cst.wsb + c0);

#pragma unroll 4
        for (int jj = 0; jj < 16; jj++) {
            int   nb = __shfl_sync(0xffffffffu, nj, jj, 16);
            float hx = __shfl_sync(0xffffffffu, h0, jj, 16);
            float hy = __shfl_sync(0xffffffffu, h1, jj, 16);
            float hz = __shfl_sync(0xffffffffu, h2, jj, 16);
            float2 kv = *(const float2*)(g_k + (size_t)nb * 64 + c0);
            float2 pe = fma2(make_float2(hx, hx), w02,
                        fma2(make_float2(hy, hy), w12,
                        fma2(make_float2(hz, hz), w22, wb2)));
            float2 arg = fma2(kv, s12, add2(xq2, pe));
            *(float2*)(rvp + jj * RV_J_STRIDE + l * 2) =
                make_float2(fmaxf(arg.x, 0.f), fmaxf(arg.y, 0.f));
        }
        __syncwarp();

        // phase A partial: lane = neighbor l; channels cb..cb+31
        {
            const float* rvj = rvp + l * RV_J_STRIDE;
#pragma unroll
            for (int c4 = 0; c4 < 8; c4++) {
                float4 rv4 = *(const float4*)(rvj + c4 * 4);
                float rvv[4] = {rv4.x, rv4.y, rv4.z, rv4.w};
#pragma unroll
                for (int ii = 0; ii < 4; ii++) {
                    const float* war = cst.wa + (cb + c4 * 4 + ii) * 8;
                    float4 wa0 = *(const float4*)(war);
                    float4 wa1 = *(const float4*)(war + 4);
                    float2 rr = make_float2(rvv[ii], rvv[ii]);
                    a2[0] = fma2(rr, make_float2(wa0.x, wa0.y), a2[0]);
                    a2[1] = fma2(rr, make_float2(wa0.z, wa0.w), a2[1]);
                    a2[2] = fma2(rr, make_float2(wa1.x, wa1.y), a2[2]);
                    a2[3] = fma2(rr, make_float2(wa1.z, wa1.w), a2[3]);
                }
            }
        }
        __syncwarp();
    }

    // ---- second MLP (8 -> 8) ----
    float2 b2[4];
#pragma unroll
    for (int q = 0; q < 4; q++) b2[q] = *(const float2*)(cst.bw + q * 2);
#pragma unroll
    for (int m = 0; m < 8; m++) {
        float avm = (m & 1) ? a2[m >> 1].y : a2[m >> 1].x;
        float t = fmaxf(fmaf(avm, cst.s2[m], cst.bb2[m]), 0.f);
        float2 tt = make_float2(t, t);
        const float2* wr = (const float2*)(cst.wbm + m * 8);
        b2[0] = fma2(tt, wr[0], b2[0]);
        b2[1] = fma2(tt, wr[1], b2[1]);
        b2[2] = fma2(tt, wr[2], b2[2]);
        b2[3] = fma2(tt, wr[3], b2[3]);
    }

    // ---- softmax over 16 neighbors, computed in place in b2 ----
    {
        // max over 8 m-values per lane pair... (per-m reduction over neighbor axis)
#pragma unroll
        for (int q = 0; q < 4; q++) {
            float2 v2 = b2[q];
            float mx0 = v2.x, mx1 = v2.y;
#pragma unroll
            for (int off = 8; off >= 1; off >>= 1) {
                mx0 = fmaxf(mx0, __shfl_xor_sync(0xffffffffu, mx0, off));
                mx1 = fmaxf(mx1, __shfl_xor_sync(0xffffffffu, mx1, off));
            }
            float e0 = __expf(v2.x - mx0);
            float e1 = __expf(v2.y - mx1);
            float s0 = e0, s1 = e1;
#pragma unroll
            for (int off = 8; off >= 1; off >>= 1) {
                s0 += __shfl_xor_sync(0xffffffffu, s0, off);
                s1 += __shfl_xor_sync(0xffffffffu, s1, off);
            }
            b2[q] = make_float2(__fdividef(e0, s0), __fdividef(e1, s1));
        }
    }
    // overlay softmax weights into this point's own (dead) rv region
    {
        float* wp = rvp + l * W_J_STRIDE;
        *(float4*)(wp)     = make_float4(b2[0].x, b2[0].y, b2[1].x, b2[1].y);
        *(float4*)(wp + 4) = make_float4(b2[2].x, b2[2].y, b2[3].x, b2[3].y);
    }
    __syncwarp();

    // ---- phase B: channel-parallel aggregation (coalesced v gather) ----
    const int c0 = l * 4;
    const int m0 = (l & 1) * 4;
    float4 rr0 = *(const float4*)(cst.r0 + c0);
    float4 rr1 = *(const float4*)(cst.r1 + c0);
    float4 rr2 = *(const float4*)(cst.r2 + c0);
    float4 rrb = *(const float4*)(cst.rb + c0);
    float2 acc01 = make_float2(0.f, 0.f), acc23 = make_float2(0.f, 0.f);
#pragma unroll 4
    for (int jj = 0; jj < 16; jj++) {
        int   nb = __shfl_sync(0xffffffffu, nj, jj, 16);
        float hx = __shfl_sync(0xffffffffu, h0, jj, 16);
        float hy = __shfl_sync(0xffffffffu, h1, jj, 16);
        float hz = __shfl_sync(0xffffffffu, h2, jj, 16);
        float4 wv = *(const float4*)(rvp + jj * W_J_STRIDE + m0);
        float4 v4 = *(const float4*)(g_v + (size_t)nb * 64 + c0);
        float2 pe01 = fma2(make_float2(hx, hx), make_float2(rr0.x, rr0.y),
                      fma2(make_float2(hy, hy), make_float2(rr1.x, rr1.y),
                      fma2(make_float2(hz, hz), make_float2(rr2.x, rr2.y),
                           make_float2(rrb.x, rrb.y))));
        float2 pe23 = fma2(make_float2(hx, hx), make_float2(rr0.z, rr0.w),
                      fma2(make_float2(hy, hy), make_float2(rr1.z, rr1.w),
                      fma2(make_float2(hz, hz), make_float2(rr2.z, rr2.w),
                           make_float2(rrb.z, rrb.w))));
        acc01 = fma2(add2(make_float2(v4.x, v4.y), pe01), make_float2(wv.x, wv.y), acc01);
        acc23 = fma2(add2(make_float2(v4.z, v4.w), pe23), make_float2(wv.z, wv.w), acc23);
    }
    if (i0 < N)
        *(float4*)(outp + (size_t)i0 * 64 + c0) =
            make_float4(acc01.x, acc01.y, acc23.x, acc23.y);
}

// ============================================================================
extern "C" void kernel_launch(void* const* d_in, const int* in_sizes, int n_in,
                              void* d_out, int out_size) {
    const float* p   = (const float*)d_in[0];
    const float* x   = (const float*)d_in[1];
    const int*   idx = (const int*)d_in[2];
    const float* Wq  = (const float*)d_in[3];  const float* bq  = (const float*)d_in[4];
    const float* Wk  = (const float*)d_in[5];  const float* bk  = (const float*)d_in[6];
    const float* Wv  = (const float*)d_in[7];  const float* bv  = (const float*)d_in[8];
    const float* Wp1 = (const float*)d_in[9];  const float* bp1 = (const float*)d_in[10];
    const float* gp  = (const float*)d_in[11]; const float* bp  = (const float*)d_in[12];
    const float* Wp2 = (const float*)d_in[13]; const float* bp2 = (const float*)d_in[14];
    const float* g1  = (const float*)d_in[15]; const float* bb1 = (const float*)d_in[16];
    const float* Wa  = (const float*)d_in[17]; const float* ba  = (const float*)d_in[18];
    const float* g2  = (const float*)d_in[19]; const float* bb2 = (const float*)d_in[20];
    const float* Wb  = (const float*)d_in[21]; const float* bw  = (const float*)d_in[22];

    int N = in_sizes[0] / 3;
    if (N > MAXN) N = MAXN;  // scratch bound (problem shape is N=100000)

    const int qkv_dyn  = 64 * 192 * (int)sizeof(float);           // 49152
    const int attn_dyn = 8 * RV_PT_STRIDE * (int)sizeof(float);   // 18432
    cudaFuncSetAttribute(qkv_kernel,  cudaFuncAttributeMaxDynamicSharedMemorySize, qkv_dyn);
    cudaFuncSetAttribute(attn_kernel, cudaFuncAttributeMaxDynamicSharedMemorySize, attn_dyn);

    qkv_kernel<<<(N + 63) / 64, 256, qkv_dyn>>>(x, p, Wq, bq, Wk, bk, Wv, bv, N);

    attn_kernel<<<(N + 7) / 8, 128, attn_dyn>>>(idx, Wp1, bp1, gp, bp, Wp2, bp2,
                                                g1, bb1, Wa, ba, g2, bb2, Wb, bw,
                                                (float*)d_out, N);
}